// round 3
// baseline (speedup 1.0000x reference)
#include <cuda_runtime.h>
#include <cuda_bf16.h>

// ---------------------------------------------------------------------------
// MetaPath2Vec skip-gram loss.
//   pos_loss = -mean(log(sigmoid(dot(h0,hc)) + 1e-15))     over 81920*6 terms
//   neg_loss = -mean(log(1 - sigmoid(dot(h0,hc)) + 1e-15)) over 409600*6 terms
//   out = pos_loss + neg_loss  (single f32 scalar)
//
// Indices are int32 on device (JAX x64 disabled downgrades int64 randint).
//
// sigmoid must replicate XLA's LogisticExpander: sig = 1/(1+exp(-x)) in f32.
// The f32 rounding of (1 + exp(-x)) makes sig == 1.0 exactly for
// x > 24*ln2 = 16.636, which is where log(1-sig+eps) cliffs to log(eps)
// (~7% of neg terms). The pos side never saturates until sigmoid < 1e-15
// (x < -34.5). A tanh-based sigmoid (clamped at 15.81 both sides) is 17%
// off — measured in R2.
// ---------------------------------------------------------------------------

__device__ double g_acc[2];   // [0] = pos term sum, [1] = neg term sum

__global__ void zero_acc_kernel() {
    if (threadIdx.x < 2) g_acc[threadIdx.x] = 0.0;
}

__device__ __forceinline__ float warp_reduce_sum(float v) {
    v += __shfl_xor_sync(0xffffffffu, v, 16);
    v += __shfl_xor_sync(0xffffffffu, v, 8);
    v += __shfl_xor_sync(0xffffffffu, v, 4);
    v += __shfl_xor_sync(0xffffffffu, v, 2);
    v += __shfl_xor_sync(0xffffffffu, v, 1);
    return v;
}

// One warp per walk. Lanes hold float4 slices of the 128-dim rows, so each
// gathered row is one fully-coalesced 512B warp transaction (4x128B lines).
__global__ void __launch_bounds__(512, 2)
walk_loss_kernel(const float* __restrict__ emb,
                 const int* __restrict__ pos_rw,
                 const int* __restrict__ neg_rw,
                 int n_pos, int n_neg)
{
    __shared__ float s_pos[16];
    __shared__ float s_neg[16];

    const int lane  = threadIdx.x & 31;
    const int wl    = threadIdx.x >> 5;                       // warp in block
    const int gwarp = (blockIdx.x * blockDim.x + threadIdx.x) >> 5;
    const int total = n_pos + n_neg;

    float pos_sum = 0.0f, neg_sum = 0.0f;

    if (gwarp < total) {
        const bool is_pos = (gwarp < n_pos);
        const int* rw = is_pos
            ? pos_rw + (size_t)gwarp * 7
            : neg_rw + (size_t)(gwarp - n_pos) * 7;

        // lanes 0..6 fetch the 7 indices, broadcast to the warp
        int my = (lane < 7) ? rw[lane] : 0;
        int i0 = __shfl_sync(0xffffffffu, my, 0);
        int i1 = __shfl_sync(0xffffffffu, my, 1);
        int i2 = __shfl_sync(0xffffffffu, my, 2);
        int i3 = __shfl_sync(0xffffffffu, my, 3);
        int i4 = __shfl_sync(0xffffffffu, my, 4);
        int i5 = __shfl_sync(0xffffffffu, my, 5);
        int i6 = __shfl_sync(0xffffffffu, my, 6);

        const float4* e = reinterpret_cast<const float4*>(emb);
        // issue all 7 row gathers before any dependent math (MLP = 28 lines)
        float4 h  = e[(size_t)i0 * 32 + lane];
        float4 v1 = e[(size_t)i1 * 32 + lane];
        float4 v2 = e[(size_t)i2 * 32 + lane];
        float4 v3 = e[(size_t)i3 * 32 + lane];
        float4 v4 = e[(size_t)i4 * 32 + lane];
        float4 v5 = e[(size_t)i5 * 32 + lane];
        float4 v6 = e[(size_t)i6 * 32 + lane];

        float d1 = h.x*v1.x + h.y*v1.y + h.z*v1.z + h.w*v1.w;
        float d2 = h.x*v2.x + h.y*v2.y + h.z*v2.z + h.w*v2.w;
        float d3 = h.x*v3.x + h.y*v3.y + h.z*v3.z + h.w*v3.w;
        float d4 = h.x*v4.x + h.y*v4.y + h.z*v4.z + h.w*v4.w;
        float d5 = h.x*v5.x + h.y*v5.y + h.z*v5.z + h.w*v5.w;
        float d6 = h.x*v6.x + h.y*v6.y + h.z*v6.z + h.w*v6.w;

        d1 = warp_reduce_sum(d1);
        d2 = warp_reduce_sum(d2);
        d3 = warp_reduce_sum(d3);
        d4 = warp_reduce_sum(d4);
        d5 = warp_reduce_sum(d5);
        d6 = warp_reduce_sum(d6);

        // compute the 6 transcendental terms in parallel across lanes 0..5
        float dv = (lane == 0) ? d1 :
                   (lane == 1) ? d2 :
                   (lane == 2) ? d3 :
                   (lane == 3) ? d4 :
                   (lane == 4) ? d5 : d6;

        // XLA LogisticExpander form, f32 literal arithmetic:
        float sig = 1.0f / (1.0f + expf(-dv));
        // replicate the reference's f32 arithmetic literally (incl. the
        // 1 - sig cancellation cliff for the neg branch)
        float arg = is_pos ? (sig + 1e-15f) : (1.0f - sig + 1e-15f);
        float term = (lane < 6) ? (-logf(arg)) : 0.0f;

        term = warp_reduce_sum(term);
        if (lane == 0) {
            if (is_pos) pos_sum = term; else neg_sum = term;
        }
    }

    if (lane == 0) { s_pos[wl] = pos_sum; s_neg[wl] = neg_sum; }
    __syncthreads();

    if (wl == 0) {
        float p = (lane < 16) ? s_pos[lane] : 0.0f;
        float n = (lane < 16) ? s_neg[lane] : 0.0f;
        p = warp_reduce_sum(p);
        n = warp_reduce_sum(n);
        if (lane == 0) {
            if (p != 0.0f) atomicAdd(&g_acc[0], (double)p);
            if (n != 0.0f) atomicAdd(&g_acc[1], (double)n);
        }
    }
}

__global__ void finalize_kernel(float* out, int n_pos, int n_neg) {
    if (threadIdx.x == 0) {
        double pos_loss = g_acc[0] / ((double)n_pos * 6.0);
        double neg_loss = g_acc[1] / ((double)n_neg * 6.0);
        out[0] = (float)(pos_loss + neg_loss);
    }
}

extern "C" void kernel_launch(void* const* d_in, const int* in_sizes, int n_in,
                              void* d_out, int out_size)
{
    const float* emb    = (const float*)d_in[0];
    const int*   pos_rw = (const int*)d_in[1];
    const int*   neg_rw = (const int*)d_in[2];

    const int n_pos = in_sizes[1] / 7;   // 81920
    const int n_neg = in_sizes[2] / 7;   // 409600
    const int total = n_pos + n_neg;     // 491520 walks, one warp each

    zero_acc_kernel<<<1, 32>>>();

    const int threads = 512;             // 16 warps
    const int wpb = threads / 32;
    const int blocks = (total + wpb - 1) / wpb;
    walk_loss_kernel<<<blocks, threads>>>(emb, pos_rw, neg_rw, n_pos, n_neg);

    finalize_kernel<<<1, 32>>>((float*)d_out, n_pos, n_neg);
}

// round 4
// speedup vs baseline: 1.0049x; 1.0049x over previous
#include <cuda_runtime.h>
#include <cuda_bf16.h>

// ---------------------------------------------------------------------------
// MetaPath2Vec skip-gram loss (pass R3: 225us, rel_err 9.5e-8).
//
// R4 change: gather embedding rows with cp.async.cg (LDGSTS) into per-warp
// smem instead of LDG. LDG in-flight lines are capped by the ~248-entry
// L1tex return queue per SM (model-matched the measured 7.8 TB/s); LDGSTS
// has no observed depth cap, so in-flight MLP rises ~2.6x and the kernel
// moves to the L2/LTS throughput limit.
//
// Numerics (validated R3): sig = 1/(1+expf(-x)) in f32, literal
// sig+1e-15f / 1-sig+1e-15f. Indices are int32 on device.
// ---------------------------------------------------------------------------

__device__ double g_acc[2];   // [0] = pos term sum, [1] = neg term sum

__global__ void zero_acc_kernel() {
    if (threadIdx.x < 2) g_acc[threadIdx.x] = 0.0;
}

__device__ __forceinline__ float warp_reduce_sum(float v) {
    v += __shfl_xor_sync(0xffffffffu, v, 16);
    v += __shfl_xor_sync(0xffffffffu, v, 8);
    v += __shfl_xor_sync(0xffffffffu, v, 4);
    v += __shfl_xor_sync(0xffffffffu, v, 2);
    v += __shfl_xor_sync(0xffffffffu, v, 1);
    return v;
}

#define CP_ASYNC_CG16(dst, src) \
    asm volatile("cp.async.cg.shared.global [%0], [%1], 16;\n" \
                 :: "r"(dst), "l"(src) : "memory")
#define CP_COMMIT() asm volatile("cp.async.commit_group;\n" ::: "memory")
#define CP_WAIT0()  asm volatile("cp.async.wait_group 0;\n" ::: "memory")

// 4 warps per CTA; each warp owns a 7-row x 512B smem staging buffer.
// Lane L copies bytes [L*16, L*16+16) of each row and reads back exactly
// those bytes -> per-thread cp.async completion is sufficient ordering.
__global__ void __launch_bounds__(128, 8)
walk_loss_kernel(const float* __restrict__ emb,
                 const int* __restrict__ pos_rw,
                 const int* __restrict__ neg_rw,
                 int n_pos, int n_neg)
{
    __shared__ float4 sbuf[4][7][32];       // 14336 B
    __shared__ double sred[2][4];

    const int lane  = threadIdx.x & 31;
    const int wl    = threadIdx.x >> 5;
    const int gw    = (blockIdx.x * blockDim.x + threadIdx.x) >> 5;
    const int W     = (gridDim.x * blockDim.x) >> 5;   // total warps
    const int total = n_pos + n_neg;

    double pos_acc = 0.0, neg_acc = 0.0;

    // index slot this lane fetches (lanes 0..6 active)
    int my = 0;
    if (gw < total) {
        const int* rw0 = (gw < n_pos) ? pos_rw + (size_t)gw * 7
                                      : neg_rw + (size_t)(gw - n_pos) * 7;
        if (lane < 7) my = rw0[lane];
    }

    const char* embc = reinterpret_cast<const char*>(emb);

    for (int w = gw; w < total; w += W) {
        // ---- prefetch indices for the NEXT walk (hides idx LDG latency) ----
        int wn = w + W;
        int my_next = 0;
        if (wn < total && lane < 7) {
            const int* rwn = (wn < n_pos) ? pos_rw + (size_t)wn * 7
                                          : neg_rw + (size_t)(wn - n_pos) * 7;
            my_next = rwn[lane];
        }

        // ---- issue 7 row gathers via cp.async (512B per row per warp) ----
        #pragma unroll
        for (int r = 0; r < 7; r++) {
            int idx = __shfl_sync(0xffffffffu, my, r);
            const char* src = embc + ((size_t)idx << 9) + (lane << 4);
            unsigned dst = (unsigned)__cvta_generic_to_shared(&sbuf[wl][r][lane]);
            CP_ASYNC_CG16(dst, src);
        }
        CP_COMMIT();
        CP_WAIT0();

        // ---- dots from smem ----
        float4 h  = sbuf[wl][0][lane];
        float4 v1 = sbuf[wl][1][lane];
        float4 v2 = sbuf[wl][2][lane];
        float4 v3 = sbuf[wl][3][lane];
        float4 v4 = sbuf[wl][4][lane];
        float4 v5 = sbuf[wl][5][lane];
        float4 v6 = sbuf[wl][6][lane];

        float d1 = h.x*v1.x + h.y*v1.y + h.z*v1.z + h.w*v1.w;
        float d2 = h.x*v2.x + h.y*v2.y + h.z*v2.z + h.w*v2.w;
        float d3 = h.x*v3.x + h.y*v3.y + h.z*v3.z + h.w*v3.w;
        float d4 = h.x*v4.x + h.y*v4.y + h.z*v4.z + h.w*v4.w;
        float d5 = h.x*v5.x + h.y*v5.y + h.z*v5.z + h.w*v5.w;
        float d6 = h.x*v6.x + h.y*v6.y + h.z*v6.z + h.w*v6.w;

        d1 = warp_reduce_sum(d1);
        d2 = warp_reduce_sum(d2);
        d3 = warp_reduce_sum(d3);
        d4 = warp_reduce_sum(d4);
        d5 = warp_reduce_sum(d5);
        d6 = warp_reduce_sum(d6);

        // 6 transcendental terms in parallel across lanes 0..5
        float dv = (lane == 0) ? d1 :
                   (lane == 1) ? d2 :
                   (lane == 2) ? d3 :
                   (lane == 3) ? d4 :
                   (lane == 4) ? d5 : d6;

        const bool is_pos = (w < n_pos);
        float sig  = 1.0f / (1.0f + expf(-dv));
        float arg  = is_pos ? (sig + 1e-15f) : (1.0f - sig + 1e-15f);
        float term = (lane < 6) ? (-logf(arg)) : 0.0f;

        term = warp_reduce_sum(term);
        if (lane == 0) {
            if (is_pos) pos_acc += (double)term;
            else        neg_acc += (double)term;
        }

        my = my_next;
    }

    if (lane == 0) { sred[0][wl] = pos_acc; sred[1][wl] = neg_acc; }
    __syncthreads();

    if (threadIdx.x == 0) {
        double p = sred[0][0] + sred[0][1] + sred[0][2] + sred[0][3];
        double n = sred[1][0] + sred[1][1] + sred[1][2] + sred[1][3];
        atomicAdd(&g_acc[0], p);
        atomicAdd(&g_acc[1], n);
    }
}

__global__ void finalize_kernel(float* out, int n_pos, int n_neg) {
    if (threadIdx.x == 0) {
        double pos_loss = g_acc[0] / ((double)n_pos * 6.0);
        double neg_loss = g_acc[1] / ((double)n_neg * 6.0);
        out[0] = (float)(pos_loss + neg_loss);
    }
}

extern "C" void kernel_launch(void* const* d_in, const int* in_sizes, int n_in,
                              void* d_out, int out_size)
{
    const float* emb    = (const float*)d_in[0];
    const int*   pos_rw = (const int*)d_in[1];
    const int*   neg_rw = (const int*)d_in[2];

    const int n_pos = in_sizes[1] / 7;   // 81920
    const int n_neg = in_sizes[2] / 7;   // 409600

    zero_acc_kernel<<<1, 32>>>();

    // 148 SMs x 8 CTAs x 4 warps = 4736 resident warps, grid-stride ~104
    // walks per warp.
    const int blocks  = 148 * 8;
    const int threads = 128;
    walk_loss_kernel<<<blocks, threads>>>(emb, pos_rw, neg_rw, n_pos, n_neg);

    finalize_kernel<<<1, 32>>>((float*)d_out, n_pos, n_neg);
}